// round 13
// baseline (speedup 1.0000x reference)
#include <cuda_runtime.h>
#include <cuda_bf16.h>
#include <cstdint>

#define N_ATOM 50000
#define M_NBR  12
#define NM_TOT 600000
#define F_DIM  128
#define FAN_IN 320
#define EPS    1e-5f
#define CH     25

typedef unsigned long long ull;

#define PACK_F32X2(out, lo, hi) \
    asm("mov.b64 %0, {%1, %2};" : "=l"(out) : "f"(lo), "f"(hi))
#define UNPACK_F32X2(lo, hi, in) \
    asm("mov.b64 {%0, %1}, %2;" : "=f"(lo), "=f"(hi) : "l"(in))
#define FMA_F32X2(acc, a, b) \
    asm("fma.rn.f32x2 %0, %1, %2, %0;" : "+l"(acc) : "l"(a), "l"(b))

// ---------------- scratch ----------------------------------------------------
__device__ __align__(16) float g_SA[(size_t)N_ATOM * 512];      // [n][0:256)=S, [256:512)=A
__device__ __align__(16) float g_gated[(size_t)NM_TOT * 256];
__device__ __align__(16) float g_nbr[(size_t)N_ATOM * F_DIM];
__device__ float g_stats1[512];
__device__ float g_stats2[256];
__device__ float g_bn1[512];
__device__ float g_bn2[256];
__device__ int   g_idx32[NM_TOT];
__device__ __align__(16) __nv_bfloat16 g_WSh[512 * 128];   // [S|A] weights hi
__device__ __align__(16) __nv_bfloat16 g_WSl[512 * 128];   // [S|A] weights lo

__device__ __forceinline__ float softplusf(float x) {
    return fmaxf(x, 0.f) + __logf(1.f + __expf(-fabsf(x)));
}
__device__ __forceinline__ float sigmoidf(float x) {
    return 1.f / (1.f + __expf(-x));
}
__device__ __forceinline__ uint32_t smem_u32(const void* p) {
    uint32_t a;
    asm("{ .reg .u64 t; cvta.to.shared.u64 t, %1; cvt.u32.u64 %0, t; }"
        : "=r"(a) : "l"(p));
    return a;
}
__device__ __forceinline__ uint32_t pkbf(__nv_bfloat16 a, __nv_bfloat16 b) {
    __nv_bfloat162 t = __halves2bfloat162(a, b);
    return *(uint32_t*)&t;
}
__device__ __forceinline__ void ldsm_x4(uint32_t* r, uint32_t addr) {
    asm volatile("ldmatrix.sync.aligned.m8n8.x4.shared.b16 {%0,%1,%2,%3}, [%4];"
        : "=r"(r[0]), "=r"(r[1]), "=r"(r[2]), "=r"(r[3]) : "r"(addr));
}
__device__ __forceinline__ void mma_bf16(float* c, const uint32_t* a,
                                         uint32_t b0, uint32_t b1) {
    asm volatile("mma.sync.aligned.m16n8k16.row.col.f32.bf16.bf16.f32 "
        "{%0,%1,%2,%3}, {%4,%5,%6,%7}, {%8,%9}, {%0,%1,%2,%3};"
        : "+f"(c[0]), "+f"(c[1]), "+f"(c[2]), "+f"(c[3])
        : "r"(a[0]), "r"(a[1]), "r"(a[2]), "r"(a[3]), "r"(b0), "r"(b1));
}

// sa kernel smem layout (98304 B)
#define SB_A 0             // 128 rows x 32 chunks x 16B ([Xh|Xl], K=128)
#define SB_W 65536         // 64 rows x 32 chunks x 16B
#define SB_TOTAL 98304

// ---------------- k_convert: is64-detect + idx normalize + zero stats --------
__global__ void k_convert(const int* __restrict__ raw) {
    __shared__ int any;
    if (threadIdx.x == 0) any = 0;
    __syncthreads();
    if (threadIdx.x < 256 && raw[threadIdx.x * 2 + 1] != 0) atomicOr(&any, 1);
    __syncthreads();
    const int is64 = (any == 0);
    int i = blockIdx.x * blockDim.x + threadIdx.x;
    if (i < NM_TOT) g_idx32[i] = is64 ? raw[2 * i] : raw[i];
    if (i < 512) g_stats1[i] = 0.f;
    if (i < 256) g_stats2[i] = 0.f;
}

// ---------------- k_wsplit: [S|A] weight split --------------------------------
__global__ void k_wsplit(const float* __restrict__ W) {
    int i = blockIdx.x * blockDim.x + threadIdx.x;
    if (i < 512 * 128) {
        int f = i >> 7, k = i & 127;
        float w = (f < 256) ? W[f * FAN_IN + k] : W[(f - 256) * FAN_IN + 128 + k];
        __nv_bfloat16 h = __float2bfloat16(w);
        g_WSh[i] = h;
        g_WSl[i] = __float2bfloat16(w - __bfloat162float(h));
    }
}

// ---------------- k1: [S|A] via HMMA bf16 hi/lo (proven) ---------------------
__global__ __launch_bounds__(256) void k_sa_hmma(const float* __restrict__ atom) {
    extern __shared__ char smem[];
    const uint32_t sb = smem_u32(smem);
    const int tid = threadIdx.x;
    const int wid = tid >> 5, lane = tid & 31;
    const int fbase = blockIdx.x * 64;
    const int row0  = blockIdx.y * 128;
    const int rw0 = wid * 16;

    for (int t = tid; t < 2048; t += 256) {
        int r = t >> 4, c = t & 15;
        int gr = row0 + r; if (gr >= N_ATOM) gr = N_ATOM - 1;
        float4 v0 = *(const float4*)(atom + (size_t)gr * 128 + c * 8);
        float4 v1 = *(const float4*)(atom + (size_t)gr * 128 + c * 8 + 4);
        float xs[8] = {v0.x, v0.y, v0.z, v0.w, v1.x, v1.y, v1.z, v1.w};
        __nv_bfloat16 h[8]; float l[8];
#pragma unroll
        for (int q = 0; q < 8; q++) {
            h[q] = __float2bfloat16(xs[q]);
            l[q] = xs[q] - __bfloat162float(h[q]);
        }
        uint4 hh = make_uint4(pkbf(h[0], h[1]), pkbf(h[2], h[3]),
                              pkbf(h[4], h[5]), pkbf(h[6], h[7]));
        uint4 ll = make_uint4(
            pkbf(__float2bfloat16(l[0]), __float2bfloat16(l[1])),
            pkbf(__float2bfloat16(l[2]), __float2bfloat16(l[3])),
            pkbf(__float2bfloat16(l[4]), __float2bfloat16(l[5])),
            pkbf(__float2bfloat16(l[6]), __float2bfloat16(l[7])));
        int base = r * 512;
        *(uint4*)(smem + SB_A + base + (((c)      ^ (r & 7)) << 4)) = hh;
        *(uint4*)(smem + SB_A + base + (((c + 16) ^ (r & 7)) << 4)) = ll;
    }
    for (int t = tid; t < 1024; t += 256) {
        int r = t >> 4, c = t & 15;
        int gf = fbase + r;
        uint4 hh = *(const uint4*)((const char*)g_WSh + (size_t)gf * 256 + c * 16);
        uint4 ll = *(const uint4*)((const char*)g_WSl + (size_t)gf * 256 + c * 16);
        int base = r * 512;
        *(uint4*)(smem + SB_W + base + (((c)      ^ (r & 7)) << 4)) = hh;
        *(uint4*)(smem + SB_W + base + (((c + 16) ^ (r & 7)) << 4)) = ll;
    }
    __syncthreads();

    float acc[8][4];
#pragma unroll
    for (int i = 0; i < 8; i++)
#pragma unroll
        for (int j = 0; j < 4; j++) acc[i][j] = 0.f;

    const int arow = rw0 + (lane & 15);
    const uint32_t a_base = sb + SB_A + arow * 512;
    const int asel = lane >> 4;
    const int brow_l = ((lane >> 4) << 3) + (lane & 7);
    const int bsel = (lane >> 3) & 1;

#pragma unroll
    for (int s = 0; s < 24; s++) {
        int grp = s >> 3, ss = s & 7;          // 0:hh 1:hl 2:lh
        int ac = ((grp == 2) ? 16 : 0) + 2 * ss + asel;
        int bc = ((grp == 1) ? 16 : 0) + 2 * ss + bsel;
        uint32_t a[4];
        ldsm_x4(a, a_base + ((ac ^ (arow & 7)) << 4));
#pragma unroll
        for (int t = 0; t < 4; t++) {
            uint32_t b[4];
            int brow = t * 16 + brow_l;
            ldsm_x4(b, sb + SB_W + brow * 512 + ((bc ^ (brow & 7)) << 4));
            mma_bf16(acc[2 * t],     a, b[0], b[1]);
            mma_bf16(acc[2 * t + 1], a, b[2], b[3]);
        }
    }

    const int g = lane >> 2, tig = lane & 3;
#pragma unroll
    for (int nt = 0; nt < 8; nt++) {
        int col = fbase + nt * 8 + tig * 2;
#pragma unroll
        for (int rr = 0; rr < 2; rr++) {
            int gr = row0 + rw0 + g + rr * 8;
            if (gr < N_ATOM)
                *(float2*)(g_SA + (size_t)gr * 512 + col) =
                    make_float2(acc[nt][rr * 2], acc[nt][rr * 2 + 1]);
        }
    }
}

// ---------------- k2: E GEMM FFMA2 (128x128 tile) + fused gated + stats ------
// grid (2, 4688), 256 threads. tx=tid&15 (cols fbase+tx*4, fbase+64+tx*4),
// ty=tid>>4 (rows ty*8..+7 as 4 lane pairs). 2 CTAs/SM.
__global__ __launch_bounds__(256, 2) void k_gemm_gate(const float* __restrict__ nbr,
                                                      const float* __restrict__ W,
                                                      const float* __restrict__ bias) {
    __shared__ __align__(16) float Xs[32][128];   // [k][row]
    __shared__ __align__(16) float Ws[32][128];   // [k][f]
    __shared__ float s_stat[256];                 // sum[128], sumsq[128]
    const int tid = threadIdx.x;
    const int tx = tid & 15, ty = tid >> 4;
    const int fbase = blockIdx.x * 128;           // 0 or 128
    const int row0  = blockIdx.y * 128;

    ull acc[4][8];
#pragma unroll
    for (int p = 0; p < 4; p++)
#pragma unroll
        for (int c = 0; c < 8; c++) acc[p][c] = 0ULL;

    for (int kc = 0; kc < 64; kc += 32) {
        for (int t = tid; t < 1024; t += 256) {
            int r = t & 127, kq = t >> 7;          // kq 0..7
            int gr = row0 + r; if (gr >= NM_TOT) gr = NM_TOT - 1;
            float4 v = *(const float4*)(nbr + (size_t)gr * 64 + kc + kq * 4);
            Xs[kq * 4 + 0][r] = v.x; Xs[kq * 4 + 1][r] = v.y;
            Xs[kq * 4 + 2][r] = v.z; Xs[kq * 4 + 3][r] = v.w;
        }
        for (int t = tid; t < 1024; t += 256) {
            int fl = t & 127, kq = t >> 7;         // kq 0..7
            float4 v = *(const float4*)(W + (size_t)(fbase + fl) * FAN_IN + 256 + kc + kq * 4);
            Ws[kq * 4 + 0][fl] = v.x; Ws[kq * 4 + 1][fl] = v.y;
            Ws[kq * 4 + 2][fl] = v.z; Ws[kq * 4 + 3][fl] = v.w;
        }
        __syncthreads();
#pragma unroll 8
        for (int k = 0; k < 32; k++) {
            ulonglong2 A01 = *(ulonglong2*)&Xs[k][ty * 8];       // rows 0-3 paired
            ulonglong2 A23 = *(ulonglong2*)&Xs[k][ty * 8 + 4];   // rows 4-7 paired
            float4 B0 = *(float4*)&Ws[k][tx * 4];
            float4 B1 = *(float4*)&Ws[k][64 + tx * 4];
            ull b[8];
            PACK_F32X2(b[0], B0.x, B0.x); PACK_F32X2(b[1], B0.y, B0.y);
            PACK_F32X2(b[2], B0.z, B0.z); PACK_F32X2(b[3], B0.w, B0.w);
            PACK_F32X2(b[4], B1.x, B1.x); PACK_F32X2(b[5], B1.y, B1.y);
            PACK_F32X2(b[6], B1.z, B1.z); PACK_F32X2(b[7], B1.w, B1.w);
            ull ap[4] = {A01.x, A01.y, A23.x, A23.y};
#pragma unroll
            for (int p = 0; p < 4; p++) {
#pragma unroll
                for (int c = 0; c < 8; c++)
                    FMA_F32X2(acc[p][c], ap[p], b[c]);
            }
        }
        __syncthreads();
    }

    // epilogue: gated = S + b + msk*(A[idx] + E); float4 stores + stats
    s_stat[tid] = 0.f;
    __syncthreads();

    const float4 bia0 = *(const float4*)(bias + fbase + tx * 4);
    const float4 bia1 = *(const float4*)(bias + fbase + 64 + tx * 4);
    float sums[8], sqs[8];
#pragma unroll
    for (int q = 0; q < 8; q++) { sums[q] = 0.f; sqs[q] = 0.f; }

#pragma unroll
    for (int p = 0; p < 4; p++) {
        float e[2][8];
#pragma unroll
        for (int c = 0; c < 8; c++)
            UNPACK_F32X2(e[0][c], e[1][c], acc[p][c]);
#pragma unroll
        for (int s = 0; s < 2; s++) {
            int nm = row0 + ty * 8 + 2 * p + s;
            if (nm >= NM_TOT) continue;
            int n = nm / 12;
            int j = g_idx32[nm];
            float msk = (j != 0) ? 1.f : 0.f;
#pragma unroll
            for (int cg = 0; cg < 2; cg++) {
                int col = fbase + cg * 64 + tx * 4;
                float4 s4 = *(const float4*)(g_SA + (size_t)n * 512 + col);
                float4 a4 = *(const float4*)(g_SA + (size_t)j * 512 + 256 + col);
                float4 bb = cg ? bia1 : bia0;
                float g0 = s4.x + bb.x + msk * (a4.x + e[s][cg * 4 + 0]);
                float g1 = s4.y + bb.y + msk * (a4.y + e[s][cg * 4 + 1]);
                float g2 = s4.z + bb.z + msk * (a4.z + e[s][cg * 4 + 2]);
                float g3 = s4.w + bb.w + msk * (a4.w + e[s][cg * 4 + 3]);
                *(float4*)(g_gated + (size_t)nm * 256 + col) =
                    make_float4(g0, g1, g2, g3);
                sums[cg * 4 + 0] += g0; sqs[cg * 4 + 0] += g0 * g0;
                sums[cg * 4 + 1] += g1; sqs[cg * 4 + 1] += g1 * g1;
                sums[cg * 4 + 2] += g2; sqs[cg * 4 + 2] += g2 * g2;
                sums[cg * 4 + 3] += g3; sqs[cg * 4 + 3] += g3 * g3;
            }
        }
    }
#pragma unroll
    for (int q = 0; q < 8; q++) {
        int lc = (q >> 2) * 64 + tx * 4 + (q & 3);
        atomicAdd(&s_stat[lc], sums[q]);
        atomicAdd(&s_stat[128 + lc], sqs[q]);
    }
    __syncthreads();
    if (tid < 128)      atomicAdd(&g_stats1[fbase + tid],             s_stat[tid]);
    else                atomicAdd(&g_stats1[256 + fbase + tid - 128], s_stat[tid]);
}

// ---------------- k3: finalize BN1 affine ------------------------------------
__global__ void k_fin1(const float* __restrict__ gamma1, const float* __restrict__ beta1) {
    int f = threadIdx.x;  // 256
    float inv = 1.f / (float)NM_TOT;
    float mean = g_stats1[f] * inv;
    float var  = g_stats1[256 + f] * inv - mean * mean;
    float sc = gamma1[f] * rsqrtf(var + EPS);
    g_bn1[f] = sc;
    g_bn1[256 + f] = beta1[f] - mean * sc;
}

// ---------------- k4: gate + sum over M + BN2 stats --------------------------
__global__ __launch_bounds__(128) void k_reduce() {
    const int f = threadIdx.x;
    const int n0 = blockIdx.x * CH;
    const float sc_f = g_bn1[f],        sh_f = g_bn1[256 + f];
    const float sc_c = g_bn1[128 + f],  sh_c = g_bn1[256 + 128 + f];
    float bs = 0.f, bq = 0.f;
    for (int n = n0; n < n0 + CH; n++) {
        float acc = 0.f;
#pragma unroll
        for (int m = 0; m < 12; m++) {
            int nm = n * 12 + m;
            int j = g_idx32[nm];
            if (j != 0) {
                float gf = g_gated[(size_t)nm * 256 + f]       * sc_f + sh_f;
                float gc = g_gated[(size_t)nm * 256 + 128 + f] * sc_c + sh_c;
                acc += sigmoidf(gf) * softplusf(gc);
            }
        }
        g_nbr[(size_t)n * 128 + f] = acc;
        bs += acc; bq += acc * acc;
    }
    atomicAdd(&g_stats2[f],       bs);
    atomicAdd(&g_stats2[128 + f], bq);
}

// ---------------- k5: finalize BN2 affine ------------------------------------
__global__ void k_fin2(const float* __restrict__ gamma2, const float* __restrict__ beta2) {
    int f = threadIdx.x;  // 128
    float inv = 1.f / (float)N_ATOM;
    float mean = g_stats2[f] * inv;
    float var  = g_stats2[128 + f] * inv - mean * mean;
    float sc = gamma2[f] * rsqrtf(var + EPS);
    g_bn2[f] = sc;
    g_bn2[128 + f] = beta2[f] - mean * sc;
}

// ---------------- k6: out = softplus(atom + BN2(nbr_sumed)) ------------------
__global__ void k_out(const float* __restrict__ atom, float* __restrict__ out) {
    int i = blockIdx.x * blockDim.x + threadIdx.x;
    if (i < N_ATOM * 128) {
        int f = i & 127;
        float v = atom[i] + g_nbr[i] * g_bn2[f] + g_bn2[128 + f];
        out[i] = softplusf(v);
    }
}

// ---------------- launch ------------------------------------------------------
extern "C" void kernel_launch(void* const* d_in, const int* in_sizes, int n_in,
                              void* d_out, int out_size) {
    const float* atom   = (const float*)d_in[0];
    const float* nbr    = (const float*)d_in[1];
    const int*   idxraw = (const int*)d_in[2];
    const float* W      = (const float*)d_in[3];
    const float* b      = (const float*)d_in[4];
    const float* gamma1 = (const float*)d_in[5];
    const float* beta1  = (const float*)d_in[6];
    const float* gamma2 = (const float*)d_in[7];
    const float* beta2  = (const float*)d_in[8];
    float* out = (float*)d_out;

    cudaFuncSetAttribute(k_sa_hmma, cudaFuncAttributeMaxDynamicSharedMemorySize, SB_TOTAL);

    k_convert<<<(NM_TOT + 255) / 256, 256>>>(idxraw);                 // 1
    k_wsplit<<<(512 * 128 + 255) / 256, 256>>>(W);                    // 2
    k_sa_hmma<<<dim3(8, (N_ATOM + 127) / 128), 256, SB_TOTAL>>>(atom);// 3
    k_gemm_gate<<<dim3(2, (NM_TOT + 127) / 128), 256>>>(nbr, W, b);   // 4 <- profiled
    k_fin1<<<1, 256>>>(gamma1, beta1);
    k_reduce<<<N_ATOM / CH, 128>>>();
    k_fin2<<<1, 128>>>(gamma2, beta2);
    k_out<<<(N_ATOM * 128 + 255) / 256, 256>>>(atom, out);
}

// round 14
// speedup vs baseline: 1.1034x; 1.1034x over previous
#include <cuda_runtime.h>
#include <cuda_bf16.h>
#include <cstdint>

#define N_ATOM 50000
#define M_NBR  12
#define NM_TOT 600000
#define F_DIM  128
#define FAN_IN 320
#define EPS    1e-5f
#define CH     25

typedef unsigned long long ull;

#define PACK_F32X2(out, lo, hi) \
    asm("mov.b64 %0, {%1, %2};" : "=l"(out) : "f"(lo), "f"(hi))
#define UNPACK_F32X2(lo, hi, in) \
    asm("mov.b64 {%0, %1}, %2;" : "=f"(lo), "=f"(hi) : "l"(in))
#define FMA_F32X2(acc, a, b) \
    asm("fma.rn.f32x2 %0, %1, %2, %0;" : "+l"(acc) : "l"(a), "l"(b))

// ---------------- scratch ----------------------------------------------------
__device__ __align__(16) float g_SA[(size_t)N_ATOM * 512];      // [n][0:256)=S, [256:512)=A
__device__ __align__(16) float g_gated[(size_t)NM_TOT * 256];
__device__ __align__(16) float g_nbr[(size_t)N_ATOM * F_DIM];
__device__ float g_stats1[512];
__device__ float g_stats2[256];
__device__ float g_bn1[512];
__device__ float g_bn2[256];
__device__ int   g_idx32[NM_TOT];
__device__ __align__(16) __nv_bfloat16 g_WSh[512 * 128];   // [S|A] weights hi
__device__ __align__(16) __nv_bfloat16 g_WSl[512 * 128];   // [S|A] weights lo

__device__ __forceinline__ float softplusf(float x) {
    return fmaxf(x, 0.f) + __logf(1.f + __expf(-fabsf(x)));
}
__device__ __forceinline__ float sigmoidf(float x) {
    return 1.f / (1.f + __expf(-x));
}
__device__ __forceinline__ uint32_t smem_u32(const void* p) {
    uint32_t a;
    asm("{ .reg .u64 t; cvta.to.shared.u64 t, %1; cvt.u32.u64 %0, t; }"
        : "=r"(a) : "l"(p));
    return a;
}
__device__ __forceinline__ uint32_t pkbf(__nv_bfloat16 a, __nv_bfloat16 b) {
    __nv_bfloat162 t = __halves2bfloat162(a, b);
    return *(uint32_t*)&t;
}
__device__ __forceinline__ void ldsm_x4(uint32_t* r, uint32_t addr) {
    asm volatile("ldmatrix.sync.aligned.m8n8.x4.shared.b16 {%0,%1,%2,%3}, [%4];"
        : "=r"(r[0]), "=r"(r[1]), "=r"(r[2]), "=r"(r[3]) : "r"(addr));
}
__device__ __forceinline__ void mma_bf16(float* c, const uint32_t* a,
                                         uint32_t b0, uint32_t b1) {
    asm volatile("mma.sync.aligned.m16n8k16.row.col.f32.bf16.bf16.f32 "
        "{%0,%1,%2,%3}, {%4,%5,%6,%7}, {%8,%9}, {%0,%1,%2,%3};"
        : "+f"(c[0]), "+f"(c[1]), "+f"(c[2]), "+f"(c[3])
        : "r"(a[0]), "r"(a[1]), "r"(a[2]), "r"(a[3]), "r"(b0), "r"(b1));
}

// sa kernel smem layout (98304 B)
#define SB_A 0             // 128 rows x 32 chunks x 16B ([Xh|Xl], K=128)
#define SB_W 65536         // 64 rows x 32 chunks x 16B
#define SB_TOTAL 98304

// ---------------- k_convert: is64-detect + idx normalize + zero stats --------
__global__ void k_convert(const int* __restrict__ raw) {
    __shared__ int any;
    if (threadIdx.x == 0) any = 0;
    __syncthreads();
    if (threadIdx.x < 256 && raw[threadIdx.x * 2 + 1] != 0) atomicOr(&any, 1);
    __syncthreads();
    const int is64 = (any == 0);
    int i = blockIdx.x * blockDim.x + threadIdx.x;
    if (i < NM_TOT) g_idx32[i] = is64 ? raw[2 * i] : raw[i];
    if (i < 512) g_stats1[i] = 0.f;
    if (i < 256) g_stats2[i] = 0.f;
}

// ---------------- k_wsplit: [S|A] weight split --------------------------------
__global__ void k_wsplit(const float* __restrict__ W) {
    int i = blockIdx.x * blockDim.x + threadIdx.x;
    if (i < 512 * 128) {
        int f = i >> 7, k = i & 127;
        float w = (f < 256) ? W[f * FAN_IN + k] : W[(f - 256) * FAN_IN + 128 + k];
        __nv_bfloat16 h = __float2bfloat16(w);
        g_WSh[i] = h;
        g_WSl[i] = __float2bfloat16(w - __bfloat162float(h));
    }
}

// ---------------- k1: [S|A] via HMMA bf16 hi/lo (proven) ---------------------
__global__ __launch_bounds__(256) void k_sa_hmma(const float* __restrict__ atom) {
    extern __shared__ char smem[];
    const uint32_t sb = smem_u32(smem);
    const int tid = threadIdx.x;
    const int wid = tid >> 5, lane = tid & 31;
    const int fbase = blockIdx.x * 64;
    const int row0  = blockIdx.y * 128;
    const int rw0 = wid * 16;

    for (int t = tid; t < 2048; t += 256) {
        int r = t >> 4, c = t & 15;
        int gr = row0 + r; if (gr >= N_ATOM) gr = N_ATOM - 1;
        float4 v0 = *(const float4*)(atom + (size_t)gr * 128 + c * 8);
        float4 v1 = *(const float4*)(atom + (size_t)gr * 128 + c * 8 + 4);
        float xs[8] = {v0.x, v0.y, v0.z, v0.w, v1.x, v1.y, v1.z, v1.w};
        __nv_bfloat16 h[8]; float l[8];
#pragma unroll
        for (int q = 0; q < 8; q++) {
            h[q] = __float2bfloat16(xs[q]);
            l[q] = xs[q] - __bfloat162float(h[q]);
        }
        uint4 hh = make_uint4(pkbf(h[0], h[1]), pkbf(h[2], h[3]),
                              pkbf(h[4], h[5]), pkbf(h[6], h[7]));
        uint4 ll = make_uint4(
            pkbf(__float2bfloat16(l[0]), __float2bfloat16(l[1])),
            pkbf(__float2bfloat16(l[2]), __float2bfloat16(l[3])),
            pkbf(__float2bfloat16(l[4]), __float2bfloat16(l[5])),
            pkbf(__float2bfloat16(l[6]), __float2bfloat16(l[7])));
        int base = r * 512;
        *(uint4*)(smem + SB_A + base + (((c)      ^ (r & 7)) << 4)) = hh;
        *(uint4*)(smem + SB_A + base + (((c + 16) ^ (r & 7)) << 4)) = ll;
    }
    for (int t = tid; t < 1024; t += 256) {
        int r = t >> 4, c = t & 15;
        int gf = fbase + r;
        uint4 hh = *(const uint4*)((const char*)g_WSh + (size_t)gf * 256 + c * 16);
        uint4 ll = *(const uint4*)((const char*)g_WSl + (size_t)gf * 256 + c * 16);
        int base = r * 512;
        *(uint4*)(smem + SB_W + base + (((c)      ^ (r & 7)) << 4)) = hh;
        *(uint4*)(smem + SB_W + base + (((c + 16) ^ (r & 7)) << 4)) = ll;
    }
    __syncthreads();

    float acc[8][4];
#pragma unroll
    for (int i = 0; i < 8; i++)
#pragma unroll
        for (int j = 0; j < 4; j++) acc[i][j] = 0.f;

    const int arow = rw0 + (lane & 15);
    const uint32_t a_base = sb + SB_A + arow * 512;
    const int asel = lane >> 4;
    const int brow_l = ((lane >> 4) << 3) + (lane & 7);
    const int bsel = (lane >> 3) & 1;

#pragma unroll
    for (int s = 0; s < 24; s++) {
        int grp = s >> 3, ss = s & 7;          // 0:hh 1:hl 2:lh
        int ac = ((grp == 2) ? 16 : 0) + 2 * ss + asel;
        int bc = ((grp == 1) ? 16 : 0) + 2 * ss + bsel;
        uint32_t a[4];
        ldsm_x4(a, a_base + ((ac ^ (arow & 7)) << 4));
#pragma unroll
        for (int t = 0; t < 4; t++) {
            uint32_t b[4];
            int brow = t * 16 + brow_l;
            ldsm_x4(b, sb + SB_W + brow * 512 + ((bc ^ (brow & 7)) << 4));
            mma_bf16(acc[2 * t],     a, b[0], b[1]);
            mma_bf16(acc[2 * t + 1], a, b[2], b[3]);
        }
    }

    const int g = lane >> 2, tig = lane & 3;
#pragma unroll
    for (int nt = 0; nt < 8; nt++) {
        int col = fbase + nt * 8 + tig * 2;
#pragma unroll
        for (int rr = 0; rr < 2; rr++) {
            int gr = row0 + rw0 + g + rr * 8;
            if (gr < N_ATOM)
                *(float2*)(g_SA + (size_t)gr * 512 + col) =
                    make_float2(acc[nt][rr * 2], acc[nt][rr * 2 + 1]);
        }
    }
}

// ---------------- k2: E GEMM FFMA2 + fused gated + BN1 stats -----------------
// BM=128 rows, BN=64 cols, grid (4, 4688), 256 threads, 4 CTAs/SM target.
__global__ __launch_bounds__(256, 4) void k_gemm_gate(const float* __restrict__ nbr,
                                                      const float* __restrict__ W,
                                                      const float* __restrict__ bias) {
    __shared__ __align__(16) float Xs[32][128];   // [k][row]
    __shared__ __align__(16) float Ws[32][64];    // [k][f]
    __shared__ float s_stat[128];                 // sum[64], sumsq[64]
    const int tid = threadIdx.x;
    const int tx = tid & 15, ty = tid >> 4;
    const int fbase = blockIdx.x * 64;            // 0,64,128,192
    const int row0  = blockIdx.y * 128;

    ull acc[4][4];
#pragma unroll
    for (int p = 0; p < 4; p++)
#pragma unroll
        for (int c = 0; c < 4; c++) acc[p][c] = 0ULL;

    for (int kc = 0; kc < 64; kc += 32) {
        for (int t = tid; t < 1024; t += 256) {
            int r = t & 127, kq = t >> 7;          // kq 0..7
            int gr = row0 + r; if (gr >= NM_TOT) gr = NM_TOT - 1;
            float4 v = *(const float4*)(nbr + (size_t)gr * 64 + kc + kq * 4);
            Xs[kq * 4 + 0][r] = v.x; Xs[kq * 4 + 1][r] = v.y;
            Xs[kq * 4 + 2][r] = v.z; Xs[kq * 4 + 3][r] = v.w;
        }
        for (int t = tid; t < 512; t += 256) {
            int fl = t & 63, kq = t >> 6;          // kq 0..7
            float4 v = *(const float4*)(W + (size_t)(fbase + fl) * FAN_IN + 256 + kc + kq * 4);
            Ws[kq * 4 + 0][fl] = v.x; Ws[kq * 4 + 1][fl] = v.y;
            Ws[kq * 4 + 2][fl] = v.z; Ws[kq * 4 + 3][fl] = v.w;
        }
        __syncthreads();
#pragma unroll 8
        for (int k = 0; k < 32; k++) {
            ulonglong2 A01 = *(ulonglong2*)&Xs[k][ty * 8];
            ulonglong2 A23 = *(ulonglong2*)&Xs[k][ty * 8 + 4];
            float4 Bv = *(float4*)&Ws[k][tx * 4];
            ull b0, b1, b2, b3;
            PACK_F32X2(b0, Bv.x, Bv.x); PACK_F32X2(b1, Bv.y, Bv.y);
            PACK_F32X2(b2, Bv.z, Bv.z); PACK_F32X2(b3, Bv.w, Bv.w);
            FMA_F32X2(acc[0][0], A01.x, b0); FMA_F32X2(acc[0][1], A01.x, b1);
            FMA_F32X2(acc[0][2], A01.x, b2); FMA_F32X2(acc[0][3], A01.x, b3);
            FMA_F32X2(acc[1][0], A01.y, b0); FMA_F32X2(acc[1][1], A01.y, b1);
            FMA_F32X2(acc[1][2], A01.y, b2); FMA_F32X2(acc[1][3], A01.y, b3);
            FMA_F32X2(acc[2][0], A23.x, b0); FMA_F32X2(acc[2][1], A23.x, b1);
            FMA_F32X2(acc[2][2], A23.x, b2); FMA_F32X2(acc[2][3], A23.x, b3);
            FMA_F32X2(acc[3][0], A23.y, b0); FMA_F32X2(acc[3][1], A23.y, b1);
            FMA_F32X2(acc[3][2], A23.y, b2); FMA_F32X2(acc[3][3], A23.y, b3);
        }
        __syncthreads();
    }

    if (tid < 128) s_stat[tid] = 0.f;
    __syncthreads();

    const float4 bia = *(const float4*)(bias + fbase + tx * 4);
    float sums[4] = {0.f, 0.f, 0.f, 0.f}, sqs[4] = {0.f, 0.f, 0.f, 0.f};

#pragma unroll
    for (int p = 0; p < 4; p++) {
        float l0, h0, l1, h1, l2, h2, l3, h3;
        UNPACK_F32X2(l0, h0, acc[p][0]);
        UNPACK_F32X2(l1, h1, acc[p][1]);
        UNPACK_F32X2(l2, h2, acc[p][2]);
        UNPACK_F32X2(l3, h3, acc[p][3]);
#pragma unroll
        for (int s = 0; s < 2; s++) {
            float e0 = s ? h0 : l0, e1 = s ? h1 : l1;
            float e2 = s ? h2 : l2, e3 = s ? h3 : l3;
            int nm = row0 + ty * 8 + 2 * p + s;
            if (nm >= NM_TOT) continue;
            int n = nm / 12;
            int j = g_idx32[nm];
            float msk = (j != 0) ? 1.f : 0.f;
            int col = fbase + tx * 4;
            float4 s4 = *(const float4*)(g_SA + (size_t)n * 512 + col);
            float4 a4 = *(const float4*)(g_SA + (size_t)j * 512 + 256 + col);
            float g0 = s4.x + bia.x + msk * (a4.x + e0);
            float g1 = s4.y + bia.y + msk * (a4.y + e1);
            float g2 = s4.z + bia.z + msk * (a4.z + e2);
            float g3 = s4.w + bia.w + msk * (a4.w + e3);
            *(float4*)(g_gated + (size_t)nm * 256 + col) = make_float4(g0, g1, g2, g3);
            sums[0] += g0; sqs[0] += g0 * g0;
            sums[1] += g1; sqs[1] += g1 * g1;
            sums[2] += g2; sqs[2] += g2 * g2;
            sums[3] += g3; sqs[3] += g3 * g3;
        }
    }
#pragma unroll
    for (int c = 0; c < 4; c++) {
        int lc = tx * 4 + c;
        atomicAdd(&s_stat[lc], sums[c]);
        atomicAdd(&s_stat[64 + lc], sqs[c]);
    }
    __syncthreads();
    if (tid < 64) {
        atomicAdd(&g_stats1[fbase + tid],       s_stat[tid]);
        atomicAdd(&g_stats1[256 + fbase + tid], s_stat[64 + tid]);
    }
}

// ---------------- k3: finalize BN1 affine ------------------------------------
__global__ void k_fin1(const float* __restrict__ gamma1, const float* __restrict__ beta1) {
    int f = threadIdx.x;  // 256
    float inv = 1.f / (float)NM_TOT;
    float mean = g_stats1[f] * inv;
    float var  = g_stats1[256 + f] * inv - mean * mean;
    float sc = gamma1[f] * rsqrtf(var + EPS);
    g_bn1[f] = sc;
    g_bn1[256 + f] = beta1[f] - mean * sc;
}

// ---------------- k4: gate + sum over M + BN2 stats --------------------------
__global__ __launch_bounds__(128) void k_reduce() {
    const int f = threadIdx.x;
    const int n0 = blockIdx.x * CH;
    const float sc_f = g_bn1[f],        sh_f = g_bn1[256 + f];
    const float sc_c = g_bn1[128 + f],  sh_c = g_bn1[256 + 128 + f];
    float bs = 0.f, bq = 0.f;
    for (int n = n0; n < n0 + CH; n++) {
        float acc = 0.f;
#pragma unroll
        for (int m = 0; m < 12; m++) {
            int nm = n * 12 + m;
            int j = g_idx32[nm];
            if (j != 0) {
                float gf = g_gated[(size_t)nm * 256 + f]       * sc_f + sh_f;
                float gc = g_gated[(size_t)nm * 256 + 128 + f] * sc_c + sh_c;
                acc += sigmoidf(gf) * softplusf(gc);
            }
        }
        g_nbr[(size_t)n * 128 + f] = acc;
        bs += acc; bq += acc * acc;
    }
    atomicAdd(&g_stats2[f],       bs);
    atomicAdd(&g_stats2[128 + f], bq);
}

// ---------------- k5: finalize BN2 affine ------------------------------------
__global__ void k_fin2(const float* __restrict__ gamma2, const float* __restrict__ beta2) {
    int f = threadIdx.x;  // 128
    float inv = 1.f / (float)N_ATOM;
    float mean = g_stats2[f] * inv;
    float var  = g_stats2[128 + f] * inv - mean * mean;
    float sc = gamma2[f] * rsqrtf(var + EPS);
    g_bn2[f] = sc;
    g_bn2[128 + f] = beta2[f] - mean * sc;
}

// ---------------- k6: out = softplus(atom + BN2(nbr_sumed)) ------------------
__global__ void k_out(const float* __restrict__ atom, float* __restrict__ out) {
    int i = blockIdx.x * blockDim.x + threadIdx.x;
    if (i < N_ATOM * 128) {
        int f = i & 127;
        float v = atom[i] + g_nbr[i] * g_bn2[f] + g_bn2[128 + f];
        out[i] = softplusf(v);
    }
}

// ---------------- launch ------------------------------------------------------
extern "C" void kernel_launch(void* const* d_in, const int* in_sizes, int n_in,
                              void* d_out, int out_size) {
    const float* atom   = (const float*)d_in[0];
    const float* nbr    = (const float*)d_in[1];
    const int*   idxraw = (const int*)d_in[2];
    const float* W      = (const float*)d_in[3];
    const float* b      = (const float*)d_in[4];
    const float* gamma1 = (const float*)d_in[5];
    const float* beta1  = (const float*)d_in[6];
    const float* gamma2 = (const float*)d_in[7];
    const float* beta2  = (const float*)d_in[8];
    float* out = (float*)d_out;

    cudaFuncSetAttribute(k_sa_hmma, cudaFuncAttributeMaxDynamicSharedMemorySize, SB_TOTAL);

    k_convert<<<(NM_TOT + 255) / 256, 256>>>(idxraw);                 // 1
    k_wsplit<<<(512 * 128 + 255) / 256, 256>>>(W);                    // 2
    k_sa_hmma<<<dim3(8, (N_ATOM + 127) / 128), 256, SB_TOTAL>>>(atom);// 3
    k_gemm_gate<<<dim3(4, (NM_TOT + 127) / 128), 256>>>(nbr, W, b);   // 4 <- profiled
    k_fin1<<<1, 256>>>(gamma1, beta1);
    k_reduce<<<N_ATOM / CH, 128>>>();
    k_fin2<<<1, 128>>>(gamma2, beta2);
    k_out<<<(N_ATOM * 128 + 255) / 256, 256>>>(atom, out);
}

// round 15
// speedup vs baseline: 1.1975x; 1.0854x over previous
#include <cuda_runtime.h>
#include <cuda_bf16.h>
#include <cstdint>

#define N_ATOM 50000
#define M_NBR  12
#define NM_TOT 600000
#define F_DIM  128
#define FAN_IN 320
#define EPS    1e-5f
#define CH     25

typedef unsigned long long ull;

#define PACK_F32X2(out, lo, hi) \
    asm("mov.b64 %0, {%1, %2};" : "=l"(out) : "f"(lo), "f"(hi))
#define UNPACK_F32X2(lo, hi, in) \
    asm("mov.b64 {%0, %1}, %2;" : "=f"(lo), "=f"(hi) : "l"(in))
#define FMA_F32X2(acc, a, b) \
    asm("fma.rn.f32x2 %0, %1, %2, %0;" : "+l"(acc) : "l"(a), "l"(b))

// ---------------- scratch ----------------------------------------------------
__device__ __align__(16) float g_SA[(size_t)N_ATOM * 512];      // [n][0:256)=S, [256:512)=A
__device__ __align__(16) float g_gated[(size_t)NM_TOT * 256];
__device__ __align__(16) float g_nbr[(size_t)N_ATOM * F_DIM];
__device__ float g_stats1[512];
__device__ float g_stats2[256];
__device__ float g_bn1[512];
__device__ float g_bn2[256];
__device__ int   g_idx32[NM_TOT];
__device__ __align__(16) __nv_bfloat16 g_WSh[512 * 128];   // [S|A] weights hi
__device__ __align__(16) __nv_bfloat16 g_WSl[512 * 128];   // [S|A] weights lo

__device__ __forceinline__ float softplusf(float x) {
    return fmaxf(x, 0.f) + __logf(1.f + __expf(-fabsf(x)));
}
__device__ __forceinline__ float sigmoidf(float x) {
    return 1.f / (1.f + __expf(-x));
}
__device__ __forceinline__ uint32_t smem_u32(const void* p) {
    uint32_t a;
    asm("{ .reg .u64 t; cvta.to.shared.u64 t, %1; cvt.u32.u64 %0, t; }"
        : "=r"(a) : "l"(p));
    return a;
}
__device__ __forceinline__ uint32_t pkbf(__nv_bfloat16 a, __nv_bfloat16 b) {
    __nv_bfloat162 t = __halves2bfloat162(a, b);
    return *(uint32_t*)&t;
}
__device__ __forceinline__ void ldsm_x4(uint32_t* r, uint32_t addr) {
    asm volatile("ldmatrix.sync.aligned.m8n8.x4.shared.b16 {%0,%1,%2,%3}, [%4];"
        : "=r"(r[0]), "=r"(r[1]), "=r"(r[2]), "=r"(r[3]) : "r"(addr));
}
__device__ __forceinline__ void mma_bf16(float* c, const uint32_t* a,
                                         uint32_t b0, uint32_t b1) {
    asm volatile("mma.sync.aligned.m16n8k16.row.col.f32.bf16.bf16.f32 "
        "{%0,%1,%2,%3}, {%4,%5,%6,%7}, {%8,%9}, {%0,%1,%2,%3};"
        : "+f"(c[0]), "+f"(c[1]), "+f"(c[2]), "+f"(c[3])
        : "r"(a[0]), "r"(a[1]), "r"(a[2]), "r"(a[3]), "r"(b0), "r"(b1));
}

// sa kernel smem layout (98304 B)
#define SB_A 0             // 128 rows x 32 chunks x 16B ([Xh|Xl], K=128)
#define SB_W 65536         // 64 rows x 32 chunks x 16B
#define SB_TOTAL 98304

// ---------------- k_convert: is64-detect + idx normalize + zero stats --------
__global__ void k_convert(const int* __restrict__ raw) {
    __shared__ int any;
    if (threadIdx.x == 0) any = 0;
    __syncthreads();
    if (threadIdx.x < 256 && raw[threadIdx.x * 2 + 1] != 0) atomicOr(&any, 1);
    __syncthreads();
    const int is64 = (any == 0);
    int i = blockIdx.x * blockDim.x + threadIdx.x;
    if (i < NM_TOT) g_idx32[i] = is64 ? raw[2 * i] : raw[i];
    if (i < 512) g_stats1[i] = 0.f;
    if (i < 256) g_stats2[i] = 0.f;
}

// ---------------- k_wsplit: [S|A] weight split --------------------------------
__global__ void k_wsplit(const float* __restrict__ W) {
    int i = blockIdx.x * blockDim.x + threadIdx.x;
    if (i < 512 * 128) {
        int f = i >> 7, k = i & 127;
        float w = (f < 256) ? W[f * FAN_IN + k] : W[(f - 256) * FAN_IN + 128 + k];
        __nv_bfloat16 h = __float2bfloat16(w);
        g_WSh[i] = h;
        g_WSl[i] = __float2bfloat16(w - __bfloat162float(h));
    }
}

// ---------------- k1: [S|A] via HMMA bf16 hi/lo (proven) ---------------------
__global__ __launch_bounds__(256) void k_sa_hmma(const float* __restrict__ atom) {
    extern __shared__ char smem[];
    const uint32_t sb = smem_u32(smem);
    const int tid = threadIdx.x;
    const int wid = tid >> 5, lane = tid & 31;
    const int fbase = blockIdx.x * 64;
    const int row0  = blockIdx.y * 128;
    const int rw0 = wid * 16;

    for (int t = tid; t < 2048; t += 256) {
        int r = t >> 4, c = t & 15;
        int gr = row0 + r; if (gr >= N_ATOM) gr = N_ATOM - 1;
        float4 v0 = *(const float4*)(atom + (size_t)gr * 128 + c * 8);
        float4 v1 = *(const float4*)(atom + (size_t)gr * 128 + c * 8 + 4);
        float xs[8] = {v0.x, v0.y, v0.z, v0.w, v1.x, v1.y, v1.z, v1.w};
        __nv_bfloat16 h[8]; float l[8];
#pragma unroll
        for (int q = 0; q < 8; q++) {
            h[q] = __float2bfloat16(xs[q]);
            l[q] = xs[q] - __bfloat162float(h[q]);
        }
        uint4 hh = make_uint4(pkbf(h[0], h[1]), pkbf(h[2], h[3]),
                              pkbf(h[4], h[5]), pkbf(h[6], h[7]));
        uint4 ll = make_uint4(
            pkbf(__float2bfloat16(l[0]), __float2bfloat16(l[1])),
            pkbf(__float2bfloat16(l[2]), __float2bfloat16(l[3])),
            pkbf(__float2bfloat16(l[4]), __float2bfloat16(l[5])),
            pkbf(__float2bfloat16(l[6]), __float2bfloat16(l[7])));
        int base = r * 512;
        *(uint4*)(smem + SB_A + base + (((c)      ^ (r & 7)) << 4)) = hh;
        *(uint4*)(smem + SB_A + base + (((c + 16) ^ (r & 7)) << 4)) = ll;
    }
    for (int t = tid; t < 1024; t += 256) {
        int r = t >> 4, c = t & 15;
        int gf = fbase + r;
        uint4 hh = *(const uint4*)((const char*)g_WSh + (size_t)gf * 256 + c * 16);
        uint4 ll = *(const uint4*)((const char*)g_WSl + (size_t)gf * 256 + c * 16);
        int base = r * 512;
        *(uint4*)(smem + SB_W + base + (((c)      ^ (r & 7)) << 4)) = hh;
        *(uint4*)(smem + SB_W + base + (((c + 16) ^ (r & 7)) << 4)) = ll;
    }
    __syncthreads();

    float acc[8][4];
#pragma unroll
    for (int i = 0; i < 8; i++)
#pragma unroll
        for (int j = 0; j < 4; j++) acc[i][j] = 0.f;

    const int arow = rw0 + (lane & 15);
    const uint32_t a_base = sb + SB_A + arow * 512;
    const int asel = lane >> 4;
    const int brow_l = ((lane >> 4) << 3) + (lane & 7);
    const int bsel = (lane >> 3) & 1;

#pragma unroll
    for (int s = 0; s < 24; s++) {
        int grp = s >> 3, ss = s & 7;          // 0:hh 1:hl 2:lh
        int ac = ((grp == 2) ? 16 : 0) + 2 * ss + asel;
        int bc = ((grp == 1) ? 16 : 0) + 2 * ss + bsel;
        uint32_t a[4];
        ldsm_x4(a, a_base + ((ac ^ (arow & 7)) << 4));
#pragma unroll
        for (int t = 0; t < 4; t++) {
            uint32_t b[4];
            int brow = t * 16 + brow_l;
            ldsm_x4(b, sb + SB_W + brow * 512 + ((bc ^ (brow & 7)) << 4));
            mma_bf16(acc[2 * t],     a, b[0], b[1]);
            mma_bf16(acc[2 * t + 1], a, b[2], b[3]);
        }
    }

    const int g = lane >> 2, tig = lane & 3;
#pragma unroll
    for (int nt = 0; nt < 8; nt++) {
        int col = fbase + nt * 8 + tig * 2;
#pragma unroll
        for (int rr = 0; rr < 2; rr++) {
            int gr = row0 + rw0 + g + rr * 8;
            if (gr < N_ATOM)
                *(float2*)(g_SA + (size_t)gr * 512 + col) =
                    make_float2(acc[nt][rr * 2], acc[nt][rr * 2 + 1]);
        }
    }
}

// ---------------- k2: E GEMM FFMA2, X resident, loop over 4 fblk --------------
// grid 4688, 256 threads, 4 CTAs/SM. Per fblk: BM=128 x BN=64, K=64.
__global__ __launch_bounds__(256, 4) void k_gemm_gate(const float* __restrict__ nbr,
                                                      const float* __restrict__ W,
                                                      const float* __restrict__ bias) {
    __shared__ __align__(16) float Xs[64][128];   // [k][row], both k-chunks (32KB)
    __shared__ __align__(16) float Ws[32][64];    // [k][f] per (fblk,kc) (8KB)
    __shared__ float s_stat[128];                 // sum[64], sumsq[64]
    const int tid = threadIdx.x;
    const int tx = tid & 15, ty = tid >> 4;
    const int row0 = blockIdx.x * 128;

    // ---- fill X once: 64 k x 128 rows ----
    for (int t = tid; t < 2048; t += 256) {
        int r = t & 127, kq = t >> 7;              // kq 0..15
        int gr = row0 + r; if (gr >= NM_TOT) gr = NM_TOT - 1;
        float4 v = *(const float4*)(nbr + (size_t)gr * 64 + kq * 4);
        Xs[kq * 4 + 0][r] = v.x; Xs[kq * 4 + 1][r] = v.y;
        Xs[kq * 4 + 2][r] = v.z; Xs[kq * 4 + 3][r] = v.w;
    }

    // per-row epilogue constants (reused across fblk)
    // each thread owns rows ty*8 + {0..7}
    for (int fblk = 0; fblk < 4; fblk++) {
        const int fbase = fblk * 64;

        ull acc[4][4];
#pragma unroll
        for (int p = 0; p < 4; p++)
#pragma unroll
            for (int c = 0; c < 4; c++) acc[p][c] = 0ULL;

        for (int kc = 0; kc < 64; kc += 32) {
            __syncthreads();   // protect Ws (and Xs on first pass)
            for (int t = tid; t < 512; t += 256) {
                int fl = t & 63, kq = t >> 6;      // kq 0..7
                float4 v = *(const float4*)(W + (size_t)(fbase + fl) * FAN_IN + 256 + kc + kq * 4);
                Ws[kq * 4 + 0][fl] = v.x; Ws[kq * 4 + 1][fl] = v.y;
                Ws[kq * 4 + 2][fl] = v.z; Ws[kq * 4 + 3][fl] = v.w;
            }
            __syncthreads();
#pragma unroll 8
            for (int k = 0; k < 32; k++) {
                ulonglong2 A01 = *(ulonglong2*)&Xs[kc + k][ty * 8];
                ulonglong2 A23 = *(ulonglong2*)&Xs[kc + k][ty * 8 + 4];
                float4 Bv = *(float4*)&Ws[k][tx * 4];
                ull b0, b1, b2, b3;
                PACK_F32X2(b0, Bv.x, Bv.x); PACK_F32X2(b1, Bv.y, Bv.y);
                PACK_F32X2(b2, Bv.z, Bv.z); PACK_F32X2(b3, Bv.w, Bv.w);
                FMA_F32X2(acc[0][0], A01.x, b0); FMA_F32X2(acc[0][1], A01.x, b1);
                FMA_F32X2(acc[0][2], A01.x, b2); FMA_F32X2(acc[0][3], A01.x, b3);
                FMA_F32X2(acc[1][0], A01.y, b0); FMA_F32X2(acc[1][1], A01.y, b1);
                FMA_F32X2(acc[1][2], A01.y, b2); FMA_F32X2(acc[1][3], A01.y, b3);
                FMA_F32X2(acc[2][0], A23.x, b0); FMA_F32X2(acc[2][1], A23.x, b1);
                FMA_F32X2(acc[2][2], A23.x, b2); FMA_F32X2(acc[2][3], A23.x, b3);
                FMA_F32X2(acc[3][0], A23.y, b0); FMA_F32X2(acc[3][1], A23.y, b1);
                FMA_F32X2(acc[3][2], A23.y, b2); FMA_F32X2(acc[3][3], A23.y, b3);
            }
        }
        __syncthreads();

        // ---- epilogue for this fblk ----
        if (tid < 128) s_stat[tid] = 0.f;
        __syncthreads();

        const float4 bia = *(const float4*)(bias + fbase + tx * 4);
        float sums[4] = {0.f, 0.f, 0.f, 0.f}, sqs[4] = {0.f, 0.f, 0.f, 0.f};

#pragma unroll
        for (int p = 0; p < 4; p++) {
            float l0, h0, l1, h1, l2, h2, l3, h3;
            UNPACK_F32X2(l0, h0, acc[p][0]);
            UNPACK_F32X2(l1, h1, acc[p][1]);
            UNPACK_F32X2(l2, h2, acc[p][2]);
            UNPACK_F32X2(l3, h3, acc[p][3]);
#pragma unroll
            for (int s = 0; s < 2; s++) {
                float e0 = s ? h0 : l0, e1 = s ? h1 : l1;
                float e2 = s ? h2 : l2, e3 = s ? h3 : l3;
                int nm = row0 + ty * 8 + 2 * p + s;
                if (nm >= NM_TOT) continue;
                int n = nm / 12;
                int j = g_idx32[nm];
                float msk = (j != 0) ? 1.f : 0.f;
                int col = fbase + tx * 4;
                float4 s4 = *(const float4*)(g_SA + (size_t)n * 512 + col);
                float4 a4 = *(const float4*)(g_SA + (size_t)j * 512 + 256 + col);
                float g0 = s4.x + bia.x + msk * (a4.x + e0);
                float g1 = s4.y + bia.y + msk * (a4.y + e1);
                float g2 = s4.z + bia.z + msk * (a4.z + e2);
                float g3 = s4.w + bia.w + msk * (a4.w + e3);
                *(float4*)(g_gated + (size_t)nm * 256 + col) = make_float4(g0, g1, g2, g3);
                sums[0] += g0; sqs[0] += g0 * g0;
                sums[1] += g1; sqs[1] += g1 * g1;
                sums[2] += g2; sqs[2] += g2 * g2;
                sums[3] += g3; sqs[3] += g3 * g3;
            }
        }
#pragma unroll
        for (int c = 0; c < 4; c++) {
            int lc = tx * 4 + c;
            atomicAdd(&s_stat[lc], sums[c]);
            atomicAdd(&s_stat[64 + lc], sqs[c]);
        }
        __syncthreads();
        if (tid < 64) {
            atomicAdd(&g_stats1[fbase + tid],       s_stat[tid]);
            atomicAdd(&g_stats1[256 + fbase + tid], s_stat[64 + tid]);
        }
    }
}

// ---------------- k3: finalize BN1 affine ------------------------------------
__global__ void k_fin1(const float* __restrict__ gamma1, const float* __restrict__ beta1) {
    int f = threadIdx.x;  // 256
    float inv = 1.f / (float)NM_TOT;
    float mean = g_stats1[f] * inv;
    float var  = g_stats1[256 + f] * inv - mean * mean;
    float sc = gamma1[f] * rsqrtf(var + EPS);
    g_bn1[f] = sc;
    g_bn1[256 + f] = beta1[f] - mean * sc;
}

// ---------------- k4: gate + sum over M + BN2 stats --------------------------
__global__ __launch_bounds__(128) void k_reduce() {
    const int f = threadIdx.x;
    const int n0 = blockIdx.x * CH;
    const float sc_f = g_bn1[f],        sh_f = g_bn1[256 + f];
    const float sc_c = g_bn1[128 + f],  sh_c = g_bn1[256 + 128 + f];
    float bs = 0.f, bq = 0.f;
    for (int n = n0; n < n0 + CH; n++) {
        float acc = 0.f;
#pragma unroll
        for (int m = 0; m < 12; m++) {
            int nm = n * 12 + m;
            int j = g_idx32[nm];
            if (j != 0) {
                float gf = g_gated[(size_t)nm * 256 + f]       * sc_f + sh_f;
                float gc = g_gated[(size_t)nm * 256 + 128 + f] * sc_c + sh_c;
                acc += sigmoidf(gf) * softplusf(gc);
            }
        }
        g_nbr[(size_t)n * 128 + f] = acc;
        bs += acc; bq += acc * acc;
    }
    atomicAdd(&g_stats2[f],       bs);
    atomicAdd(&g_stats2[128 + f], bq);
}

// ---------------- k5: finalize BN2 affine ------------------------------------
__global__ void k_fin2(const float* __restrict__ gamma2, const float* __restrict__ beta2) {
    int f = threadIdx.x;  // 128
    float inv = 1.f / (float)N_ATOM;
    float mean = g_stats2[f] * inv;
    float var  = g_stats2[128 + f] * inv - mean * mean;
    float sc = gamma2[f] * rsqrtf(var + EPS);
    g_bn2[f] = sc;
    g_bn2[128 + f] = beta2[f] - mean * sc;
}

// ---------------- k6: out = softplus(atom + BN2(nbr_sumed)) ------------------
__global__ void k_out(const float* __restrict__ atom, float* __restrict__ out) {
    int i = blockIdx.x * blockDim.x + threadIdx.x;
    if (i < N_ATOM * 128) {
        int f = i & 127;
        float v = atom[i] + g_nbr[i] * g_bn2[f] + g_bn2[128 + f];
        out[i] = softplusf(v);
    }
}

// ---------------- launch ------------------------------------------------------
extern "C" void kernel_launch(void* const* d_in, const int* in_sizes, int n_in,
                              void* d_out, int out_size) {
    const float* atom   = (const float*)d_in[0];
    const float* nbr    = (const float*)d_in[1];
    const int*   idxraw = (const int*)d_in[2];
    const float* W      = (const float*)d_in[3];
    const float* b      = (const float*)d_in[4];
    const float* gamma1 = (const float*)d_in[5];
    const float* beta1  = (const float*)d_in[6];
    const float* gamma2 = (const float*)d_in[7];
    const float* beta2  = (const float*)d_in[8];
    float* out = (float*)d_out;

    cudaFuncSetAttribute(k_sa_hmma, cudaFuncAttributeMaxDynamicSharedMemorySize, SB_TOTAL);

    k_convert<<<(NM_TOT + 255) / 256, 256>>>(idxraw);                 // 1
    k_wsplit<<<(512 * 128 + 255) / 256, 256>>>(W);                    // 2
    k_sa_hmma<<<dim3(8, (N_ATOM + 127) / 128), 256, SB_TOTAL>>>(atom);// 3
    k_gemm_gate<<<(NM_TOT + 127) / 128, 256>>>(nbr, W, b);            // 4 <- profiled
    k_fin1<<<1, 256>>>(gamma1, beta1);
    k_reduce<<<N_ATOM / CH, 128>>>();
    k_fin2<<<1, 128>>>(gamma2, beta2);
    k_out<<<(N_ATOM * 128 + 255) / 256, 256>>>(atom, out);
}